// round 3
// baseline (speedup 1.0000x reference)
#include <cuda_runtime.h>

// Problem constants
#define Bq   2
#define Sq   2048
#define Dq   768
#define Hq   12
#define HDq  64
#define Mrows (Bq * Sq)   // 4096

// Scratch (device globals: allocation-free)
__device__ float g_Q[Mrows * Dq];
__device__ float g_K[Mrows * Dq];
__device__ float g_V[Mrows * Dq];
__device__ float g_A[Mrows * Dq];

__device__ __forceinline__ float ex2f(float x) {
    float y;
    asm("ex2.approx.ftz.f32 %0, %1;" : "=f"(y) : "f"(x));
    return y;
}

// ---------------------------------------------------------------------------
// GEMM: C[M,N] = A[M,K] @ W[K,N] + bias[N]    (M=4096, N=K=768)
// 128x128 CTA tile, 8x8 micro-tile, BK=16. 256 threads as 16x16 (ty,tx).
// Thread (ty,tx) owns C rows {ty+16a}, cols {tx+16b}.
// ---------------------------------------------------------------------------
#define GBM 128
#define GBN 128
#define GBK 16
#define BS_STRIDE (GBK + 4)   // 20 floats: 16B-row-pitch = 5 -> conflict-free f4 reads

__global__ __launch_bounds__(256, 2) void gemm_bias_kernel(
    const float* __restrict__ A, const float* __restrict__ W,
    const float* __restrict__ bias, float* __restrict__ C)
{
    const int N = Dq, K = Dq;
    __shared__ __align__(16) float As[GBM * GBK];       // [m][k]
    __shared__ __align__(16) float Bs[GBN * BS_STRIDE]; // [n][k] (transposed W tile)

    const int tid = threadIdx.x;
    const int tx = tid & 15, ty = tid >> 4;
    const int m0 = blockIdx.x * GBM, n0 = blockIdx.y * GBN;

    float acc[8][8];
#pragma unroll
    for (int a = 0; a < 8; a++)
#pragma unroll
        for (int b = 0; b < 8; b++) acc[a][b] = 0.f;

    for (int k0 = 0; k0 < K; k0 += GBK) {
        // A tile: 128x16 floats = 512 float4, 2 per thread (coalesced)
#pragma unroll
        for (int i = 0; i < 2; i++) {
            int idx = tid * 2 + i;              // float4 index
            int m = idx >> 2, kk = (idx & 3) << 2;
            *(float4*)&As[m * GBK + kk] =
                *(const float4*)&A[(size_t)(m0 + m) * K + k0 + kk];
        }
        // W tile: 16x128, stored transposed as Bs[n][k] (coalesced gmem reads)
#pragma unroll
        for (int i = 0; i < 8; i++) {
            int idx = tid + 256 * i;            // 0..2047
            int kk = idx >> 7, n = idx & 127;
            Bs[n * BS_STRIDE + kk] = W[(size_t)(k0 + kk) * N + n0 + n];
        }
        __syncthreads();

#pragma unroll
        for (int kk = 0; kk < GBK; kk += 4) {
            float4 a4[8];
#pragma unroll
            for (int a = 0; a < 8; a++)
                a4[a] = *(const float4*)&As[(ty + 16 * a) * GBK + kk]; // broadcast
#pragma unroll
            for (int b = 0; b < 8; b++) {
                float4 b4 = *(const float4*)&Bs[(tx + 16 * b) * BS_STRIDE + kk];
#pragma unroll
                for (int a = 0; a < 8; a++)
                    acc[a][b] += a4[a].x * b4.x + a4[a].y * b4.y +
                                 a4[a].z * b4.z + a4[a].w * b4.w;
            }
        }
        __syncthreads();
    }

#pragma unroll
    for (int a = 0; a < 8; a++) {
        size_t m = (size_t)(m0 + ty + 16 * a);
#pragma unroll
        for (int b = 0; b < 8; b++) {
            int n = n0 + tx + 16 * b;
            C[m * N + n] = acc[a][b] + bias[n];
        }
    }
}

// ---------------------------------------------------------------------------
// Fused flash attention (fp32, no mask — matches reference).
// Grid: (S/128, H, B). 256 threads as 16x16.
// Per CTA: 128 queries; stream 16 key/value tiles of 128.
// Thread (ty,tx): score rows {ty+16a}, score cols {tx+16b}, O cols {4tx..4tx+3}.
// ---------------------------------------------------------------------------
#define AQT 128
#define AKT 128
#define QV_STRIDE 68    // 64 + 4 pad: 16B-row-pitch = 17 -> conflict-free
#define SS_STRIDE 132   // 128 + 4 pad

#define ATTN_SMEM_FLOATS (3 * AQT * QV_STRIDE + AQT * SS_STRIDE + 3 * AQT)
#define ATTN_SMEM_BYTES  (ATTN_SMEM_FLOATS * 4)

__global__ __launch_bounds__(256, 1) void attn_kernel(
    const float* __restrict__ Qg, const float* __restrict__ Kg,
    const float* __restrict__ Vg, float* __restrict__ Og)
{
    extern __shared__ __align__(16) float sm[];
    float* Qs   = sm;                        // [128][68]
    float* Ks   = Qs + AQT * QV_STRIDE;      // [128][68]
    float* Vs   = Ks + AKT * QV_STRIDE;      // [128][68]
    float* Ss   = Vs + AKT * QV_STRIDE;      // [128][132] — P tile
    float* mrow = Ss + AQT * SS_STRIDE;      // [128] running max (base-2 domain)
    float* lrow = mrow + AQT;                // [128] running sum
    float* arow = lrow + AQT;                // [128] rescale factor

    const int tid = threadIdx.x;
    const int tx = tid & 15, ty = tid >> 4;
    const int q0 = blockIdx.x * AQT;
    const int h = blockIdx.y, b = blockIdx.z;
    const size_t base = (size_t)b * Sq * Dq + (size_t)h * HDq;

    // Load Q tile: 128 rows x 64 floats (16 f4/row, coalesced)
#pragma unroll
    for (int i = 0; i < 8; i++) {
        int idx = tid + 256 * i;
        int r = idx >> 4, c = (idx & 15) << 2;
        *(float4*)&Qs[r * QV_STRIDE + c] =
            *(const float4*)&Qg[base + (size_t)(q0 + r) * Dq + c];
    }
    if (tid < AQT) { mrow[tid] = -1e30f; lrow[tid] = 0.f; }

    float oacc[8][4];
#pragma unroll
    for (int a = 0; a < 8; a++)
#pragma unroll
        for (int c = 0; c < 4; c++) oacc[a][c] = 0.f;

    __syncthreads();

    // scale * log2(e): softmax done in base-2 domain
    const float scl = 0.125f * 1.4426950408889634f;

    for (int kt = 0; kt < Sq / AKT; kt++) {
        const int k0 = kt * AKT;
        // Load K and V tiles
#pragma unroll
        for (int i = 0; i < 8; i++) {
            int idx = tid + 256 * i;
            int r = idx >> 4, c = (idx & 15) << 2;
            size_t g = base + (size_t)(k0 + r) * Dq + c;
            *(float4*)&Ks[r * QV_STRIDE + c] = *(const float4*)&Kg[g];
            *(float4*)&Vs[r * QV_STRIDE + c] = *(const float4*)&Vg[g];
        }
        __syncthreads();

        // S = (Q @ K^T) * scl  (kept in registers)
        float sacc[8][8];
#pragma unroll
        for (int a = 0; a < 8; a++)
#pragma unroll
            for (int bb = 0; bb < 8; bb++) sacc[a][bb] = 0.f;

        for (int d0 = 0; d0 < HDq; d0 += 4) {
            float4 a4[8];
#pragma unroll
            for (int a = 0; a < 8; a++)
                a4[a] = *(const float4*)&Qs[(ty + 16 * a) * QV_STRIDE + d0];
#pragma unroll
            for (int bb = 0; bb < 8; bb++) {
                float4 b4 = *(const float4*)&Ks[(tx + 16 * bb) * QV_STRIDE + d0];
#pragma unroll
                for (int a = 0; a < 8; a++)
                    sacc[a][bb] += a4[a].x * b4.x + a4[a].y * b4.y +
                                   a4[a].z * b4.z + a4[a].w * b4.w;
            }
        }

        // Per-row tile max (shfl over the 16 tx lanes of each half-warp),
        // then lane tx==0 updates running max / alpha / scales l.
#pragma unroll
        for (int a = 0; a < 8; a++) {
            float tmax = -1e30f;
#pragma unroll
            for (int bb = 0; bb < 8; bb++) {
                sacc[a][bb] *= scl;
                tmax = fmaxf(tmax, sacc[a][bb]);
            }
#pragma unroll
            for (int off = 8; off > 0; off >>= 1)
                tmax = fmaxf(tmax, __shfl_xor_sync(0xffffffffu, tmax, off, 16));
            if (tx == 0) {
                int r = ty + 16 * a;
                float mo = mrow[r];
                float mn = fmaxf(mo, tmax);
                float al = ex2f(mo - mn);
                mrow[r] = mn; arow[r] = al; lrow[r] *= al;
            }
        }
        // row r is owned entirely by its half-warp (ty = r & 15): warp sync suffices
        __syncwarp();

        // P = exp2(S - m), write P to smem, accumulate row sums, rescale O
#pragma unroll
        for (int a = 0; a < 8; a++) {
            int r = ty + 16 * a;
            float mn = mrow[r];
            float al = arow[r];
            float s = 0.f;
#pragma unroll
            for (int bb = 0; bb < 8; bb++) {
                float p = ex2f(sacc[a][bb] - mn);
                Ss[r * SS_STRIDE + tx + 16 * bb] = p;
                s += p;
            }
#pragma unroll
            for (int off = 8; off > 0; off >>= 1)
                s += __shfl_xor_sync(0xffffffffu, s, off, 16);
            if (tx == 0) lrow[r] += s;
#pragma unroll
            for (int c = 0; c < 4; c++) oacc[a][c] *= al;
        }
        __syncwarp();

        // O += P @ V   (P rows broadcast within half-warp, V f4 conflict-free)
        for (int k = 0; k < AKT; k += 4) {
            float4 v0 = *(const float4*)&Vs[(k + 0) * QV_STRIDE + (tx << 2)];
            float4 v1 = *(const float4*)&Vs[(k + 1) * QV_STRIDE + (tx << 2)];
            float4 v2 = *(const float4*)&Vs[(k + 2) * QV_STRIDE + (tx << 2)];
            float4 v3 = *(const float4*)&Vs[(k + 3) * QV_STRIDE + (tx << 2)];
#pragma unroll
            for (int a = 0; a < 8; a++) {
                float4 p = *(const float4*)&Ss[(ty + 16 * a) * SS_STRIDE + k];
                oacc[a][0] += p.x * v0.x + p.y * v1.x + p.z * v2.x + p.w * v3.x;
                oacc[a][1] += p.x * v0.y + p.y * v1.y + p.z * v2.y + p.w * v3.y;
                oacc[a][2] += p.x * v0.z + p.y * v1.z + p.z * v2.z + p.w * v3.z;
                oacc[a][3] += p.x * v0.w + p.y * v1.w + p.z * v2.w + p.w * v3.w;
            }
        }
        __syncthreads();  // before next tile overwrites Ks/Vs; also publishes lrow
    }

    // Finalize: divide by l, write [B,S,D]-layout attention output
#pragma unroll
    for (int a = 0; a < 8; a++) {
        int r = ty + 16 * a;
        float inv = 1.f / lrow[r];
        float4 o;
        o.x = oacc[a][0] * inv;
        o.y = oacc[a][1] * inv;
        o.z = oacc[a][2] * inv;
        o.w = oacc[a][3] * inv;
        *(float4*)&Og[base + (size_t)(q0 + r) * Dq + (tx << 2)] = o;
    }
}

// ---------------------------------------------------------------------------
extern "C" void kernel_launch(void* const* d_in, const int* in_sizes, int n_in,
                              void* d_out, int out_size)
{
    const float* query = (const float*)d_in[0];
    const float* key_  = (const float*)d_in[1];
    const float* value = (const float*)d_in[2];
    const float* Wq = (const float*)d_in[3];
    const float* bq = (const float*)d_in[4];
    const float* Wk = (const float*)d_in[5];
    const float* bk = (const float*)d_in[6];
    const float* Wv = (const float*)d_in[7];
    const float* bv = (const float*)d_in[8];
    const float* Wo = (const float*)d_in[9];
    const float* bo = (const float*)d_in[10];
    float* out = (float*)d_out;

    float *pQ, *pK, *pV, *pA;
    cudaGetSymbolAddress((void**)&pQ, g_Q);
    cudaGetSymbolAddress((void**)&pK, g_K);
    cudaGetSymbolAddress((void**)&pV, g_V);
    cudaGetSymbolAddress((void**)&pA, g_A);

    cudaFuncSetAttribute(attn_kernel,
                         cudaFuncAttributeMaxDynamicSharedMemorySize,
                         ATTN_SMEM_BYTES);

    dim3 gb(Mrows / GBM, Dq / GBN);   // (32, 6)
    gemm_bias_kernel<<<gb, 256>>>(query, Wq, bq, pQ);
    gemm_bias_kernel<<<gb, 256>>>(key_,  Wk, bk, pK);
    gemm_bias_kernel<<<gb, 256>>>(value, Wv, bv, pV);

    dim3 ga(Sq / AQT, Hq, Bq);        // (16, 12, 2)
    attn_kernel<<<ga, 256, ATTN_SMEM_BYTES>>>(pQ, pK, pV, pA);

    gemm_bias_kernel<<<gb, 256>>>(pA, Wo, bo, out);
}